// round 1
// baseline (speedup 1.0000x reference)
#include <cuda_runtime.h>

// Problem constants
#define Hh 768
#define Lq 384
#define Bq 2
#define NROWS (Bq * Lq)           // 768 rows of (b, l)
#define M_PAIRS 73920             // 384*385/2

// Scratch: A (with bias folded) and Bv, each [B, L, H] fp32
__device__ float g_A[NROWS * Hh];
__device__ float g_Bv[NROWS * Hh];

// ---------------------------------------------------------------------------
// Kernel 1: A[b,l,h] = sum_k seq[b,l,k] * W[h,k]          + bias[h]   (part 0)
//           Bv[b,l,h] = sum_k seq[b,l,k] * W[h, 768 + k]              (part 1)
// Classic register-tiled SGEMM: BM=64, BN=64, BK=16, 256 threads, 4x4 microtile.
// Both operands are K-contiguous (dot products of rows).
// ---------------------------------------------------------------------------
__global__ __launch_bounds__(256) void gemm_kernel(const float* __restrict__ X,
                                                   const float* __restrict__ W,
                                                   const float* __restrict__ bias) {
    const int part = blockIdx.z;
    const int row0 = blockIdx.y * 64;   // (b,l) row tile
    const int col0 = blockIdx.x * 64;   // h tile

    __shared__ float As[16][68];        // [k][row], padded stride 68 (16B-aligned rows)
    __shared__ float Bs[16][68];        // [k][col]

    const int tid = threadIdx.x;
    const int tn = tid & 15;            // 0..15 -> 4 cols each
    const int tm = tid >> 4;            // 0..15 -> 4 rows each

    const int lk = tid & 15;            // k lane for loads
    const int lr = tid >> 4;            // row lane base (16 per pass, 4 passes)

    const float* Wp = W + part * 768;   // row h of this half: Wp + h*1536 + k

    float acc[4][4];
#pragma unroll
    for (int i = 0; i < 4; i++)
#pragma unroll
        for (int j = 0; j < 4; j++) acc[i][j] = 0.0f;

    for (int k0 = 0; k0 < 768; k0 += 16) {
#pragma unroll
        for (int p = 0; p < 4; p++) {
            const int r = lr + p * 16;
            As[lk][r] = X[(row0 + r) * 768 + k0 + lk];
            Bs[lk][r] = Wp[(col0 + r) * 1536 + k0 + lk];
        }
        __syncthreads();

#pragma unroll
        for (int kk = 0; kk < 16; kk++) {
            const float4 a4 = *reinterpret_cast<const float4*>(&As[kk][tm * 4]);
            const float4 b4 = *reinterpret_cast<const float4*>(&Bs[kk][tn * 4]);
            const float ar[4] = {a4.x, a4.y, a4.z, a4.w};
            const float br[4] = {b4.x, b4.y, b4.z, b4.w};
#pragma unroll
            for (int i = 0; i < 4; i++)
#pragma unroll
                for (int j = 0; j < 4; j++) acc[i][j] += ar[i] * br[j];
        }
        __syncthreads();
    }

    float* dst = (part == 0) ? g_A : g_Bv;
    float4 bb = make_float4(0.f, 0.f, 0.f, 0.f);
    if (part == 0) bb = *reinterpret_cast<const float4*>(bias + col0 + tn * 4);

#pragma unroll
    for (int i = 0; i < 4; i++) {
        const int r = row0 + tm * 4 + i;
        float4 v;
        v.x = acc[i][0] + bb.x;
        v.y = acc[i][1] + bb.y;
        v.z = acc[i][2] + bb.z;
        v.w = acc[i][3] + bb.w;
        *reinterpret_cast<float4*>(dst + r * 768 + col0 + tn * 4) = v;
    }
}

// ---------------------------------------------------------------------------
// Fast, accurate tanh: tanh(z) = 1 - 2/(exp(2z)+1).
// __expf -> FMUL + MUFU.EX2 (rel err ~2^-22); __fdividef -> MUFU.RCP + FMUL.
// Handles saturation naturally (e=inf -> 1, e=0 -> -1). ~4 fma ops + 2 MUFU.
// ---------------------------------------------------------------------------
__device__ __forceinline__ float fast_tanh(float z) {
    const float e = __expf(2.0f * z);
    return 1.0f - __fdividef(2.0f, e + 1.0f);
}

// ---------------------------------------------------------------------------
// Kernel 2: out[b, m(i,j), h] = tanh(A[b,i,h] + Bv[b,j,h]) for j >= i.
// Block tile: IT=4 i-rows x JT=8 j-rows; 192 threads, 1 float4 (4 h) each.
// Per block: reads 12 rows (36 KB, L2-hot), writes up to 32 rows (96 KB).
// ---------------------------------------------------------------------------
__global__ __launch_bounds__(192) void pairs_kernel(float* __restrict__ out) {
    const int b  = blockIdx.z;
    const int i0 = blockIdx.y * 4;
    const int j0 = blockIdx.x * 8;
    if (j0 + 8 <= i0) return;           // tile entirely below diagonal

    const int t = threadIdx.x;          // h chunk: elements [4t, 4t+4)
    const int h0 = t * 4;

    // Load 4 A rows and 8 Bv rows (this thread's h-slice) up front: MLP=12.
    float4 a[4];
#pragma unroll
    for (int ii = 0; ii < 4; ii++)
        a[ii] = *reinterpret_cast<const float4*>(g_A + (size_t)(b * Lq + i0 + ii) * Hh + h0);

    float4 bv[8];
#pragma unroll
    for (int jj = 0; jj < 8; jj++)
        bv[jj] = *reinterpret_cast<const float4*>(g_Bv + (size_t)(b * Lq + j0 + jj) * Hh + h0);

#pragma unroll
    for (int ii = 0; ii < 4; ii++) {
        const int i = i0 + ii;
        // m = i*L - i*(i-1)/2 + (j - i)  ->  rowbase + j
        const int rowbase = i * Lq - (i * (i - 1)) / 2 - i;
        float* obase = out + ((size_t)(b * M_PAIRS + rowbase + j0)) * Hh + h0;
#pragma unroll
        for (int jj = 0; jj < 8; jj++) {
            const int j = j0 + jj;
            if (j >= i) {
                float4 v;
                v.x = fast_tanh(a[ii].x + bv[jj].x);
                v.y = fast_tanh(a[ii].y + bv[jj].y);
                v.z = fast_tanh(a[ii].z + bv[jj].z);
                v.w = fast_tanh(a[ii].w + bv[jj].w);
                *reinterpret_cast<float4*>(obase + (size_t)jj * Hh) = v;
            }
        }
    }
}

// ---------------------------------------------------------------------------
// Launch: inputs per metadata order: seq_hiddens [2,384,768] f32,
// W [768,1536] f32, b [768] f32. Output [2, 73920, 768] f32.
// ---------------------------------------------------------------------------
extern "C" void kernel_launch(void* const* d_in, const int* in_sizes, int n_in,
                              void* d_out, int out_size) {
    const float* seq  = (const float*)d_in[0];
    const float* W    = (const float*)d_in[1];
    const float* bias = (const float*)d_in[2];
    float* out = (float*)d_out;

    dim3 g1(12, 12, 2);   // (N/64, M/64, part)
    gemm_kernel<<<g1, 256>>>(seq, W, bias);

    dim3 g2(48, 96, 2);   // (384/8 j-tiles, 384/4 i-tiles, batch)
    pairs_kernel<<<g2, 192>>>(out);
}

// round 2
// speedup vs baseline: 1.1927x; 1.1927x over previous
#include <cuda_runtime.h>

// Problem constants
#define Hh 768
#define Lq 384
#define Bq 2
#define NROWS (Bq * Lq)           // 768 rows of (b, l)
#define M_PAIRS 73920             // 384*385/2

// Scratch: A (with bias folded) and Bv, each [B, L, H] fp32
__device__ float g_A[NROWS * Hh];
__device__ float g_Bv[NROWS * Hh];

// ---------------------------------------------------------------------------
// f32x2 packed-FMA helpers (Blackwell FFMA2 — 2 fp32 FMA per instruction)
// ---------------------------------------------------------------------------
typedef unsigned long long u64;

__device__ __forceinline__ u64 pack2(float lo, float hi) {
    u64 r;
    asm("mov.b64 %0, {%1, %2};" : "=l"(r) : "f"(lo), "f"(hi));
    return r;
}
__device__ __forceinline__ u64 fma2(u64 a, u64 b, u64 c) {
    u64 d;
    asm("fma.rn.f32x2 %0, %1, %2, %3;" : "=l"(d) : "l"(a), "l"(b), "l"(c));
    return d;
}
__device__ __forceinline__ float2 unpack2(u64 v) {
    float2 f;
    asm("mov.b64 {%0, %1}, %2;" : "=f"(f.x), "=f"(f.y) : "l"(v));
    return f;
}

// ---------------------------------------------------------------------------
// Kernel 1 (FFMA2 SGEMM): C[row, n] = sum_k X[row,k] * W[h(n), part(n)*768+k]
// N = 1536 combined (part 0 -> g_A with bias folded, part 1 -> g_Bv).
// BM=64, BN=128, BK=16, 256 threads, 4(M) x 8(N) microtile as 4x4 f32x2.
// Grid 12x12 = 144 blocks = one wave on 148 SMs. Double-buffered smem.
// ---------------------------------------------------------------------------
__global__ __launch_bounds__(256) void gemm_kernel(const float* __restrict__ X,
                                                   const float* __restrict__ W,
                                                   const float* __restrict__ bias) {
    const int col0 = blockIdx.x * 128;      // n tile (0..1535)
    const int row0 = blockIdx.y * 64;       // (b,l) row tile
    const int part = (col0 >= Hh) ? 1 : 0;
    const int h0b  = col0 - part * Hh;      // h base within this part

    __shared__ float As[2][16][68];         // [buf][k][m], row stride 68 (16B-aligned)
    __shared__ float Bs[2][16][132];        // [buf][k][n]

    const int tid = threadIdx.x;
    // Global-load lanes
    const int xr = tid >> 2;                // 0..63
    const int lk = (tid & 3) * 4;           // k offset 0,4,8,12
    // Compute lanes
    const int tm = tid >> 4;                // 0..15 -> 4 M rows
    const int tn = tid & 15;                // 0..15 -> cols tn*4 and 64+tn*4

    const float* Xb = X + (size_t)row0 * Hh;
    const float* Wb = W + (size_t)h0b * 1536 + part * Hh;

    u64 acc[4][4];
#pragma unroll
    for (int i = 0; i < 4; i++)
#pragma unroll
        for (int j = 0; j < 4; j++) acc[i][j] = 0ull;

    float4 xv, wv0, wv1;

#define LOAD_GLB(K0)                                                          \
    do {                                                                      \
        xv  = *reinterpret_cast<const float4*>(Xb + (size_t)xr * Hh + (K0) + lk);        \
        wv0 = *reinterpret_cast<const float4*>(Wb + (size_t)xr * 1536 + (K0) + lk);      \
        wv1 = *reinterpret_cast<const float4*>(Wb + (size_t)(xr + 64) * 1536 + (K0) + lk);\
    } while (0)

#define STORE_SM(BUF)                                                         \
    do {                                                                      \
        As[BUF][lk + 0][xr] = xv.x;  As[BUF][lk + 1][xr] = xv.y;              \
        As[BUF][lk + 2][xr] = xv.z;  As[BUF][lk + 3][xr] = xv.w;              \
        Bs[BUF][lk + 0][xr] = wv0.x; Bs[BUF][lk + 1][xr] = wv0.y;             \
        Bs[BUF][lk + 2][xr] = wv0.z; Bs[BUF][lk + 3][xr] = wv0.w;             \
        Bs[BUF][lk + 0][xr + 64] = wv1.x; Bs[BUF][lk + 1][xr + 64] = wv1.y;   \
        Bs[BUF][lk + 2][xr + 64] = wv1.z; Bs[BUF][lk + 3][xr + 64] = wv1.w;   \
    } while (0)

    LOAD_GLB(0);
    STORE_SM(0);
    __syncthreads();

    for (int t = 0; t < 48; ++t) {
        const int buf = t & 1;
        if (t + 1 < 48) LOAD_GLB((t + 1) * 16);

#pragma unroll
        for (int kk = 0; kk < 16; kk++) {
            const float4 a4 = *reinterpret_cast<const float4*>(&As[buf][kk][tm * 4]);
            const float4 b0 = *reinterpret_cast<const float4*>(&Bs[buf][kk][tn * 4]);
            const float4 b1 = *reinterpret_cast<const float4*>(&Bs[buf][kk][64 + tn * 4]);
            u64 ad[4], bp[4];
            ad[0] = pack2(a4.x, a4.x); ad[1] = pack2(a4.y, a4.y);
            ad[2] = pack2(a4.z, a4.z); ad[3] = pack2(a4.w, a4.w);
            bp[0] = pack2(b0.x, b0.y); bp[1] = pack2(b0.z, b0.w);
            bp[2] = pack2(b1.x, b1.y); bp[3] = pack2(b1.z, b1.w);
#pragma unroll
            for (int i = 0; i < 4; i++)
#pragma unroll
                for (int j = 0; j < 4; j++) acc[i][j] = fma2(ad[i], bp[j], acc[i][j]);
        }

        if (t + 1 < 48) {
            __syncthreads();
            STORE_SM(buf ^ 1);
            __syncthreads();
        }
    }

    // Epilogue: unpack, add bias (part 0), store to scratch
    float* dst = part ? g_Bv : g_A;
    const int hb = h0b + tn * 4;
    float4 bb0 = make_float4(0.f, 0.f, 0.f, 0.f);
    float4 bb1 = bb0;
    if (part == 0) {
        bb0 = *reinterpret_cast<const float4*>(bias + hb);
        bb1 = *reinterpret_cast<const float4*>(bias + hb + 64);
    }

#pragma unroll
    for (int i = 0; i < 4; i++) {
        const int row = row0 + tm * 4 + i;
        float2 p0 = unpack2(acc[i][0]);
        float2 p1 = unpack2(acc[i][1]);
        float2 p2 = unpack2(acc[i][2]);
        float2 p3 = unpack2(acc[i][3]);
        float4 v0 = make_float4(p0.x + bb0.x, p0.y + bb0.y, p1.x + bb0.z, p1.y + bb0.w);
        float4 v1 = make_float4(p2.x + bb1.x, p2.y + bb1.y, p3.x + bb1.z, p3.y + bb1.w);
        *reinterpret_cast<float4*>(dst + (size_t)row * Hh + hb)      = v0;
        *reinterpret_cast<float4*>(dst + (size_t)row * Hh + hb + 64) = v1;
    }
}

// ---------------------------------------------------------------------------
// Fast, accurate tanh: tanh(z) = 1 - 2/(exp(2z)+1).
// ---------------------------------------------------------------------------
__device__ __forceinline__ float fast_tanh(float z) {
    const float e = __expf(2.0f * z);
    return 1.0f - __fdividef(2.0f, e + 1.0f);
}

// ---------------------------------------------------------------------------
// Kernel 2: out[b, m(i,j), h] = tanh(A[b,i,h] + Bv[b,j,h]) for j >= i.
// Block tile: IT=4 i-rows x JT=8 j-rows; 192 threads, 1 float4 (4 h) each.
// Streaming stores (__stcs) keep A/Bv resident in L2.
// ---------------------------------------------------------------------------
__global__ __launch_bounds__(192) void pairs_kernel(float* __restrict__ out) {
    const int b  = blockIdx.z;
    const int i0 = blockIdx.y * 4;
    const int j0 = blockIdx.x * 8;
    if (j0 + 8 <= i0) return;           // tile entirely below diagonal

    const int t = threadIdx.x;          // h chunk: elements [4t, 4t+4)
    const int h0 = t * 4;

    float4 a[4];
#pragma unroll
    for (int ii = 0; ii < 4; ii++)
        a[ii] = *reinterpret_cast<const float4*>(g_A + (size_t)(b * Lq + i0 + ii) * Hh + h0);

    float4 bv[8];
#pragma unroll
    for (int jj = 0; jj < 8; jj++)
        bv[jj] = *reinterpret_cast<const float4*>(g_Bv + (size_t)(b * Lq + j0 + jj) * Hh + h0);

#pragma unroll
    for (int ii = 0; ii < 4; ii++) {
        const int i = i0 + ii;
        // m = i*L - i*(i-1)/2 + (j - i)  ->  rowbase + j
        const int rowbase = i * Lq - (i * (i - 1)) / 2 - i;
        float* obase = out + ((size_t)(b * M_PAIRS + rowbase + j0)) * Hh + h0;
#pragma unroll
        for (int jj = 0; jj < 8; jj++) {
            const int j = j0 + jj;
            if (j >= i) {
                float4 v;
                v.x = fast_tanh(a[ii].x + bv[jj].x);
                v.y = fast_tanh(a[ii].y + bv[jj].y);
                v.z = fast_tanh(a[ii].z + bv[jj].z);
                v.w = fast_tanh(a[ii].w + bv[jj].w);
                __stcs(reinterpret_cast<float4*>(obase + (size_t)jj * Hh), v);
            }
        }
    }
}

// ---------------------------------------------------------------------------
// Launch: seq_hiddens [2,384,768] f32, W [768,1536] f32, b [768] f32.
// Output [2, 73920, 768] f32.
// ---------------------------------------------------------------------------
extern "C" void kernel_launch(void* const* d_in, const int* in_sizes, int n_in,
                              void* d_out, int out_size) {
    const float* seq  = (const float*)d_in[0];
    const float* W    = (const float*)d_in[1];
    const float* bias = (const float*)d_in[2];
    float* out = (float*)d_out;

    dim3 g1(12, 12);      // (N/128, M/64) = 144 blocks, one wave
    gemm_kernel<<<g1, 256>>>(seq, W, bias);

    dim3 g2(48, 96, 2);   // (384/8 j-tiles, 384/4 i-tiles, batch)
    pairs_kernel<<<g2, 192>>>(out);
}

// round 4
// speedup vs baseline: 1.3308x; 1.1158x over previous
#include <cuda_runtime.h>
#include <cuda_bf16.h>
#include <cstdint>

// Problem constants
#define Hh 768
#define Lq 384
#define Bq 2
#define NROWS (Bq * Lq)           // 768 rows of (b, l)
#define M_PAIRS 73920             // 384*385/2
#define NXE (768 * 768)           // X elements
#define NWE (1536 * 768)          // W elements (as 1536 virtual K-major rows)

// Scratch
__device__ float g_A[NROWS * Hh];             // X @ W[:, :768]^T + bias
__device__ float g_Bv[NROWS * Hh];            // X @ W[:, 768:]^T
__device__ __align__(16) __nv_bfloat16 g_Xh[NXE];
__device__ __align__(16) __nv_bfloat16 g_Xl[NXE];
__device__ __align__(16) __nv_bfloat16 g_Wh[NWE];
__device__ __align__(16) __nv_bfloat16 g_Wl[NWE];

__device__ __forceinline__ uint32_t smem_u32(const void* p) {
    uint32_t a;
    asm("{ .reg .u64 t; cvta.to.shared.u64 t, %1; cvt.u32.u64 %0, t; }" : "=r"(a) : "l"(p));
    return a;
}

// ---------------------------------------------------------------------------
// Kernel 0: fp32 -> bf16 hi/lo split of X and W.
// W is re-packed into 1536 K-major virtual rows: row n = p*768 + h holds
// W[h, p*768 + k] for k in [0,768).
// ---------------------------------------------------------------------------
__device__ __forceinline__ void split_bf(float v, __nv_bfloat16& h, __nv_bfloat16& l) {
    h = __float2bfloat16(v);
    l = __float2bfloat16(v - __bfloat162float(h));
}

__global__ __launch_bounds__(256) void convert_kernel(const float* __restrict__ X,
                                                      const float* __restrict__ W) {
    const int e = (blockIdx.x * 256 + threadIdx.x) * 2;
    if (e < NXE) {
        const float2 v = *reinterpret_cast<const float2*>(X + e);
        __nv_bfloat16 h0, l0, h1, l1;
        split_bf(v.x, h0, l0);
        split_bf(v.y, h1, l1);
        *reinterpret_cast<__nv_bfloat162*>(&g_Xh[e]) = __nv_bfloat162(h0, h1);
        *reinterpret_cast<__nv_bfloat162*>(&g_Xl[e]) = __nv_bfloat162(l0, l1);
    } else if (e < NXE + NWE) {
        const int e2 = e - NXE;
        const int n = e2 / 768;
        const int k = e2 - n * 768;
        const int p = (n >= 768);
        const int h = n - p * 768;
        const float2 v = *reinterpret_cast<const float2*>(W + (size_t)h * 1536 + p * 768 + k);
        __nv_bfloat16 h0, l0, h1, l1;
        split_bf(v.x, h0, l0);
        split_bf(v.y, h1, l1);
        *reinterpret_cast<__nv_bfloat162*>(&g_Wh[e2]) = __nv_bfloat162(h0, h1);
        *reinterpret_cast<__nv_bfloat162*>(&g_Wl[e2]) = __nv_bfloat162(l0, l1);
    }
}

// ---------------------------------------------------------------------------
// Kernel 1: split-bf16 tensor-core GEMM via mma.sync (sm_100-legal HMMA path).
// D[m, n] = sum_k X[m,k] * Wv[n,k]  via  Ah*Bh + Ah*Bl + Al*Bh  (fp32 accum).
// CTA tile M=128 x N=64, 8 warps (4m x 2n, warp tile 32x32), BK=16,
// double-buffered smem, ldmatrix.x4 from 24-short-padded rows (conflict-free).
// Grid (24, 6) = 144 CTAs = one wave.
// ---------------------------------------------------------------------------
__device__ __forceinline__ void ldsm4(uint32_t& r0, uint32_t& r1, uint32_t& r2,
                                      uint32_t& r3, uint32_t addr) {
    asm volatile("ldmatrix.sync.aligned.m8n8.x4.shared.b16 {%0,%1,%2,%3}, [%4];"
                 : "=r"(r0), "=r"(r1), "=r"(r2), "=r"(r3) : "r"(addr));
}
__device__ __forceinline__ void mma16816(float* d, const uint32_t* a, const uint32_t* b) {
    asm volatile(
        "mma.sync.aligned.m16n8k16.row.col.f32.bf16.bf16.f32 "
        "{%0,%1,%2,%3}, {%4,%5,%6,%7}, {%8,%9}, {%0,%1,%2,%3};"
        : "+f"(d[0]), "+f"(d[1]), "+f"(d[2]), "+f"(d[3])
        : "r"(a[0]), "r"(a[1]), "r"(a[2]), "r"(a[3]), "r"(b[0]), "r"(b[1]));
}

__global__ __launch_bounds__(256) void mma_gemm(const float* __restrict__ bias) {
    // [buf][hi/lo][row][24 shorts] — row stride 48B (bank-conflict-free LDSM)
    __shared__ __align__(16) unsigned short sA[2][2][128][24];   // 24 KB
    __shared__ __align__(16) unsigned short sB[2][2][64][24];    // 12 KB

    const int tid = threadIdx.x;
    const int wid = tid >> 5, lane = tid & 31;
    const int wm = wid >> 1, wn = wid & 1;        // warp grid 4(m) x 2(n)
    const int col0 = blockIdx.x * 64;             // virtual-W-row tile (0..1535)
    const int row0 = blockIdx.y * 128;            // X-row tile (0..767)
    const int part = (col0 >= Hh);
    const int hb = col0 - part * Hh;

    // Global-load lanes
    const int ar = tid >> 1, ah = (tid & 1) * 8;          // A: row, col(8-elem half)
    const int br = tid >> 2, bq = (tid & 3) * 4;          // B: row, col(4-elem quarter)
    const __nv_bfloat16* Axh = g_Xh + (size_t)(row0 + ar) * 768 + ah;
    const __nv_bfloat16* Axl = g_Xl + (size_t)(row0 + ar) * 768 + ah;
    const __nv_bfloat16* Bwh = g_Wh + (size_t)(col0 + br) * 768 + bq;
    const __nv_bfloat16* Bwl = g_Wl + (size_t)(col0 + br) * 768 + bq;

    // ldmatrix source addresses (per lane), computed once
    const int aq = lane >> 3, al8 = lane & 7;
    // A quads: q0: rows+0 c0 | q1: rows+8 c0 | q2: rows+0 c8 | q3: rows+8 c8
    const int a_row = wm * 32 + (aq & 1) * 8 + al8;
    const int a_col = (aq >> 1) * 8;
    // B quads: q0: rows+0 c0 | q1: rows+0 c8 | q2: rows+8 c0 | q3: rows+8 c8
    const int b_row0 = wn * 32 + (aq >> 1) * 8 + al8;
    const int b_col = (aq & 1) * 8;

    float acc[2][4][4];
#pragma unroll
    for (int i = 0; i < 2; i++)
#pragma unroll
        for (int j = 0; j < 4; j++)
#pragma unroll
            for (int c = 0; c < 4; c++) acc[i][j][c] = 0.0f;

    uint4 avh, avl;
    uint2 bvh, bvl;

#define G_LOAD(K0)                                                          \
    do {                                                                    \
        avh = *reinterpret_cast<const uint4*>(Axh + (K0));                  \
        avl = *reinterpret_cast<const uint4*>(Axl + (K0));                  \
        bvh = *reinterpret_cast<const uint2*>(Bwh + (K0));                  \
        bvl = *reinterpret_cast<const uint2*>(Bwl + (K0));                  \
    } while (0)

#define S_STORE(BUF)                                                        \
    do {                                                                    \
        *reinterpret_cast<uint4*>(&sA[BUF][0][ar][ah]) = avh;               \
        *reinterpret_cast<uint4*>(&sA[BUF][1][ar][ah]) = avl;               \
        *reinterpret_cast<uint2*>(&sB[BUF][0][br][bq]) = bvh;               \
        *reinterpret_cast<uint2*>(&sB[BUF][1][br][bq]) = bvl;               \
    } while (0)

    G_LOAD(0);
    S_STORE(0);
    __syncthreads();

    for (int t = 0; t < 48; ++t) {
        const int buf = t & 1;
        if (t + 1 < 48) G_LOAD((t + 1) * 16);

        // Load fragments for this 16-K chunk
        uint32_t Afh[2][4], Afl[2][4];   // [m-frag][reg]
        uint32_t Bfh[4][2], Bfl[4][2];   // [n-frag][reg]
#pragma unroll
        for (int fm = 0; fm < 2; fm++) {
            const uint32_t pa_h = smem_u32(&sA[buf][0][a_row + fm * 16][a_col]);
            const uint32_t pa_l = smem_u32(&sA[buf][1][a_row + fm * 16][a_col]);
            ldsm4(Afh[fm][0], Afh[fm][1], Afh[fm][2], Afh[fm][3], pa_h);
            ldsm4(Afl[fm][0], Afl[fm][1], Afl[fm][2], Afl[fm][3], pa_l);
        }
#pragma unroll
        for (int fp = 0; fp < 2; fp++) {  // each x4 covers 2 n8 frags
            const uint32_t pb_h = smem_u32(&sB[buf][0][b_row0 + fp * 16][b_col]);
            const uint32_t pb_l = smem_u32(&sB[buf][1][b_row0 + fp * 16][b_col]);
            ldsm4(Bfh[fp * 2][0], Bfh[fp * 2][1], Bfh[fp * 2 + 1][0], Bfh[fp * 2 + 1][1], pb_h);
            ldsm4(Bfl[fp * 2][0], Bfl[fp * 2][1], Bfl[fp * 2 + 1][0], Bfl[fp * 2 + 1][1], pb_l);
        }

#pragma unroll
        for (int fm = 0; fm < 2; fm++)
#pragma unroll
            for (int fn = 0; fn < 4; fn++) {
                mma16816(acc[fm][fn], Afh[fm], Bfh[fn]);
                mma16816(acc[fm][fn], Afh[fm], Bfl[fn]);
                mma16816(acc[fm][fn], Afl[fm], Bfh[fn]);
            }

        if (t + 1 < 48) {
            __syncthreads();
            S_STORE(buf ^ 1);
            __syncthreads();
        }
    }

    // Epilogue: acc -> g_A (with bias) / g_Bv
    float* dst = part ? g_Bv : g_A;
    const int r_base = row0 + wm * 32 + (lane >> 2);
    const int c_base = hb + wn * 32 + (lane & 3) * 2;
#pragma unroll
    for (int fm = 0; fm < 2; fm++)
#pragma unroll
        for (int fn = 0; fn < 4; fn++) {
            const int cc = c_base + fn * 8;
            float2 b0 = make_float2(0.f, 0.f);
            if (!part) b0 = *reinterpret_cast<const float2*>(bias + cc);
#pragma unroll
            for (int hr = 0; hr < 2; hr++) {
                const int rr = r_base + fm * 16 + hr * 8;
                float2 v;
                v.x = acc[fm][fn][hr * 2 + 0] + b0.x;
                v.y = acc[fm][fn][hr * 2 + 1] + b0.y;
                *reinterpret_cast<float2*>(dst + (size_t)rr * Hh + cc) = v;
            }
        }
}

// ---------------------------------------------------------------------------
// Fast tanh: tanh(z) = 1 - 2/(exp(2z)+1).
// ---------------------------------------------------------------------------
__device__ __forceinline__ float fast_tanh(float z) {
    const float e = __expf(2.0f * z);
    return 1.0f - __fdividef(2.0f, e + 1.0f);
}

// ---------------------------------------------------------------------------
// Kernel 2: out[b, m(i,j), h] = tanh(A[b,i,h] + Bv[b,j,h]) for j >= i.
// IT=4 x JT=8 tile, 192 threads, float4 per thread. At the HBM write floor.
// ---------------------------------------------------------------------------
__global__ __launch_bounds__(192) void pairs_kernel(float* __restrict__ out) {
    const int b  = blockIdx.z;
    const int i0 = blockIdx.y * 4;
    const int j0 = blockIdx.x * 8;
    if (j0 + 8 <= i0) return;

    const int t = threadIdx.x;
    const int h0 = t * 4;

    float4 a[4];
#pragma unroll
    for (int ii = 0; ii < 4; ii++)
        a[ii] = *reinterpret_cast<const float4*>(g_A + (size_t)(b * Lq + i0 + ii) * Hh + h0);

    float4 bv[8];
#pragma unroll
    for (int jj = 0; jj < 8; jj++)
        bv[jj] = *reinterpret_cast<const float4*>(g_Bv + (size_t)(b * Lq + j0 + jj) * Hh + h0);

#pragma unroll
    for (int ii = 0; ii < 4; ii++) {
        const int i = i0 + ii;
        const int rowbase = i * Lq - (i * (i - 1)) / 2 - i;
        float* obase = out + ((size_t)(b * M_PAIRS + rowbase + j0)) * Hh + h0;
#pragma unroll
        for (int jj = 0; jj < 8; jj++) {
            const int j = j0 + jj;
            if (j >= i) {
                float4 v;
                v.x = fast_tanh(a[ii].x + bv[jj].x);
                v.y = fast_tanh(a[ii].y + bv[jj].y);
                v.z = fast_tanh(a[ii].z + bv[jj].z);
                v.w = fast_tanh(a[ii].w + bv[jj].w);
                __stcs(reinterpret_cast<float4*>(obase + (size_t)jj * Hh), v);
            }
        }
    }
}

// ---------------------------------------------------------------------------
// Launch: seq_hiddens [2,384,768] f32, W [768,1536] f32, b [768] f32.
// Output [2, 73920, 768] f32.
// ---------------------------------------------------------------------------
extern "C" void kernel_launch(void* const* d_in, const int* in_sizes, int n_in,
                              void* d_out, int out_size) {
    const float* seq  = (const float*)d_in[0];
    const float* W    = (const float*)d_in[1];
    const float* bias = (const float*)d_in[2];
    float* out = (float*)d_out;

    convert_kernel<<<(NXE + NWE) / 512, 256>>>(seq, W);

    dim3 g1(24, 6);       // (N/64 over 1536, M/128 over 768) = 144 CTAs
    mma_gemm<<<g1, 256>>>(bias);

    dim3 g2(48, 96, 2);   // (384/8 j-tiles, 384/4 i-tiles, batch)
    pairs_kernel<<<g2, 192>>>(out);
}